// round 6
// baseline (speedup 1.0000x reference)
#include <cuda_runtime.h>

typedef unsigned long long ull;

#define TLEN 512
#define BSZ  128
#define MDIM 31
#define HSZ  512
#define ESZ  256
#define SSZ  128
#define G3   1536
#define TB   65536      // TLEN*BSZ
#define NSTEP 511
#define NGRU_BLK 128
#define HS_SLICE 65536  // BSZ*HSZ
#define NPAIR 65408     // 511*128
#define NB4B  8176      // NPAIR/8
#define LOG2PI 1.8378770664093453f

// k3 v5 dynamic smem partition (in ull units)
#define SW_ULL    6144          // [512 k][2 uu][6]  = 48KB  (pk2(w,w) per (k,u,g))
#define SPART_ULL 12288         // [16 kq][3 g][4 u][64 iq] = 96KB
#define K3_SMEM_BYTES ((SW_ULL + SPART_ULL) * 8)   // 147456

// ---------------- scratch (device globals; no allocation) ----------------
__device__ float g_phi[TB * ESZ];                    //  64 MB   [t*128+i][e]
__device__ float g_xg[(size_t)TB * G3];              // 402 MB   TRANSPOSED: [t][col(1536)][i(128)]
__device__ float g_hs[(size_t)TLEN * BSZ * HSZ];     // 134 MB   [t][i][k]   (built by k3t)
__device__ float g_hsT[(size_t)TLEN * BSZ * HSZ];    // 134 MB   [t][k][i]
__device__ float g_he[(size_t)TB * SSZ];             //  33 MB
__device__ float g_partial[NB4B];
__device__ unsigned g_arrive;

// ---------------- f32x2 packed-FMA helpers ----------------
__device__ __forceinline__ ull pk2(float x, float y) {
    ull r; asm("mov.b64 %0, {%1, %2};" : "=l"(r) : "f"(x), "f"(y)); return r;
}
__device__ __forceinline__ ull fma2(ull a, ull b, ull c) {
    ull d; asm("fma.rn.f32x2 %0, %1, %2, %3;" : "=l"(d) : "l"(a), "l"(b), "l"(c)); return d;
}
__device__ __forceinline__ float2 up2(ull v) {
    float2 f; asm("mov.b64 {%0, %1}, %2;" : "=f"(f.x), "=f"(f.y) : "l"(v)); return f;
}
__device__ __forceinline__ float sigm(float v) { return 1.f / (1.f + __expf(-v)); }

// ---------------- K0: init ----------------
__global__ void k0_init() {
    int idx = blockIdx.x * 256 + threadIdx.x;
    if (idx < HS_SLICE) g_hsT[idx] = 0.f;
    if (idx == 0) g_arrive = 0u;
}

// ---------------- K1: phi = relu(x @ W_embed^T + b_embed) ----------------
__global__ void __launch_bounds__(256) k1_embed(const float* __restrict__ x,
                                                const float* __restrict__ W_embed,
                                                const float* __restrict__ b_embed) {
    __shared__ float sx[64][32];
    const int tid = threadIdx.x;
    const int row0 = blockIdx.x * 64;
    for (int idx = tid; idx < 64 * MDIM; idx += 256) {
        int r = idx / MDIM, c = idx - r * MDIM;
        sx[r][c] = x[(size_t)(row0 + r) * MDIM + c];
    }
    float wreg[MDIM];
    const float* wp = W_embed + tid * MDIM;
#pragma unroll
    for (int k = 0; k < MDIM; k++) wreg[k] = __ldg(wp + k);
    float bb = __ldg(b_embed + tid);
    __syncthreads();
#pragma unroll 4
    for (int r = 0; r < 64; r++) {
        float acc = bb;
#pragma unroll
        for (int k = 0; k < MDIM; k++) acc += sx[r][k] * wreg[k];
        g_phi[(size_t)(row0 + r) * ESZ + tid] = fmaxf(acc, 0.f);
    }
}

// ---------------- K2: xgT[t][col][i] = phi[t,i,:] . W_ih[col,:] + b_ih[col] ----------------
__global__ void __launch_bounds__(256) k2_gatesT(const float* __restrict__ W_ih,
                                                 const float* __restrict__ b_ih) {
    __shared__ float As[16][128];
    __shared__ float Bs[16][128];
    const int tid = threadIdx.x;
    const int t = blockIdx.z;
    const int m0 = blockIdx.x * 128;
    const float* A = W_ih;                                 // [1536][256]
    const float* B = g_phi + (size_t)t * BSZ * ESZ;        // [128][256]
    float*       C = g_xg  + (size_t)t * G3 * BSZ;         // [1536][128]
    const int lr = tid >> 1, ls = (tid & 1) * 8;
    const int tx = tid & 15, ty = tid >> 4;
    ull acc[8][4];
#pragma unroll
    for (int i = 0; i < 8; i++)
#pragma unroll
        for (int j = 0; j < 4; j++) acc[i][j] = 0ull;

    const float* Ap = A + (size_t)(m0 + lr) * ESZ + ls;
    const float* Bp = B + (size_t)lr * ESZ + ls;

    for (int kt = 0; kt < ESZ; kt += 16) {
        float4 a0 = *(const float4*)(Ap + kt);
        float4 a1 = *(const float4*)(Ap + kt + 4);
        float4 b0 = *(const float4*)(Bp + kt);
        float4 b1 = *(const float4*)(Bp + kt + 4);
        __syncthreads();
        As[ls + 0][lr] = a0.x; As[ls + 1][lr] = a0.y; As[ls + 2][lr] = a0.z; As[ls + 3][lr] = a0.w;
        As[ls + 4][lr] = a1.x; As[ls + 5][lr] = a1.y; As[ls + 6][lr] = a1.z; As[ls + 7][lr] = a1.w;
        Bs[ls + 0][lr] = b0.x; Bs[ls + 1][lr] = b0.y; Bs[ls + 2][lr] = b0.z; Bs[ls + 3][lr] = b0.w;
        Bs[ls + 4][lr] = b1.x; Bs[ls + 5][lr] = b1.y; Bs[ls + 6][lr] = b1.z; Bs[ls + 7][lr] = b1.w;
        __syncthreads();
#pragma unroll
        for (int k = 0; k < 16; k++) {
            float4 av0 = *(const float4*)&As[k][ty * 8];
            float4 av1 = *(const float4*)&As[k][ty * 8 + 4];
            float4 bv0 = *(const float4*)&Bs[k][tx * 8];
            float4 bv1 = *(const float4*)&Bs[k][tx * 8 + 4];
            ull bp0 = pk2(bv0.x, bv0.y), bp1 = pk2(bv0.z, bv0.w);
            ull bp2 = pk2(bv1.x, bv1.y), bp3 = pk2(bv1.z, bv1.w);
            float aa[8] = {av0.x, av0.y, av0.z, av0.w, av1.x, av1.y, av1.z, av1.w};
#pragma unroll
            for (int i = 0; i < 8; i++) {
                ull ap = pk2(aa[i], aa[i]);
                acc[i][0] = fma2(ap, bp0, acc[i][0]);
                acc[i][1] = fma2(ap, bp1, acc[i][1]);
                acc[i][2] = fma2(ap, bp2, acc[i][2]);
                acc[i][3] = fma2(ap, bp3, acc[i][3]);
            }
        }
    }
#pragma unroll
    for (int i = 0; i < 8; i++) {
        int row = m0 + ty * 8 + i;                 // col index in xgT
        float brow = __ldg(b_ih + row);
        float out[8]; float2 v;
        v = up2(acc[i][0]); out[0] = v.x; out[1] = v.y;
        v = up2(acc[i][1]); out[2] = v.x; out[3] = v.y;
        v = up2(acc[i][2]); out[4] = v.x; out[5] = v.y;
        v = up2(acc[i][3]); out[6] = v.x; out[7] = v.y;
#pragma unroll
        for (int j = 0; j < 8; j++) out[j] += brow;
        float4* dst = (float4*)(C + (size_t)row * BSZ + tx * 8);
        dst[0] = make_float4(out[0], out[1], out[2], out[3]);
        dst[1] = make_float4(out[4], out[5], out[6], out[7]);
    }
}

// ---------------- K4a: he = relu(hs @ W_he^T + b_he) ----------------
__global__ void __launch_bounds__(256) k4a_he(const float* __restrict__ W_he,
                                              const float* __restrict__ b_he) {
    __shared__ float As[16][128];
    __shared__ float Bs[16][128];
    const int tid = threadIdx.x;
    const int m0 = blockIdx.x * 128, n0 = 0;
    const float* A = g_hs;
    const float* B = W_he;
    const int lr = tid >> 1, ls = (tid & 1) * 8;
    const int tx = tid & 15, ty = tid >> 4;
    ull acc[8][4];
#pragma unroll
    for (int i = 0; i < 8; i++)
#pragma unroll
        for (int j = 0; j < 4; j++) acc[i][j] = 0ull;

    const float* Ap = A + (size_t)(m0 + lr) * HSZ + ls;
    const float* Bp = B + (size_t)(n0 + lr) * HSZ + ls;

    for (int kt = 0; kt < HSZ; kt += 16) {
        float4 a0 = *(const float4*)(Ap + kt);
        float4 a1 = *(const float4*)(Ap + kt + 4);
        float4 b0 = *(const float4*)(Bp + kt);
        float4 b1 = *(const float4*)(Bp + kt + 4);
        __syncthreads();
        As[ls + 0][lr] = a0.x; As[ls + 1][lr] = a0.y; As[ls + 2][lr] = a0.z; As[ls + 3][lr] = a0.w;
        As[ls + 4][lr] = a1.x; As[ls + 5][lr] = a1.y; As[ls + 6][lr] = a1.z; As[ls + 7][lr] = a1.w;
        Bs[ls + 0][lr] = b0.x; Bs[ls + 1][lr] = b0.y; Bs[ls + 2][lr] = b0.z; Bs[ls + 3][lr] = b0.w;
        Bs[ls + 4][lr] = b1.x; Bs[ls + 5][lr] = b1.y; Bs[ls + 6][lr] = b1.z; Bs[ls + 7][lr] = b1.w;
        __syncthreads();
#pragma unroll
        for (int k = 0; k < 16; k++) {
            float4 av0 = *(const float4*)&As[k][ty * 8];
            float4 av1 = *(const float4*)&As[k][ty * 8 + 4];
            float4 bv0 = *(const float4*)&Bs[k][tx * 8];
            float4 bv1 = *(const float4*)&Bs[k][tx * 8 + 4];
            ull bp0 = pk2(bv0.x, bv0.y), bp1 = pk2(bv0.z, bv0.w);
            ull bp2 = pk2(bv1.x, bv1.y), bp3 = pk2(bv1.z, bv1.w);
            float aa[8] = {av0.x, av0.y, av0.z, av0.w, av1.x, av1.y, av1.z, av1.w};
#pragma unroll
            for (int i = 0; i < 8; i++) {
                ull ap = pk2(aa[i], aa[i]);
                acc[i][0] = fma2(ap, bp0, acc[i][0]);
                acc[i][1] = fma2(ap, bp1, acc[i][1]);
                acc[i][2] = fma2(ap, bp2, acc[i][2]);
                acc[i][3] = fma2(ap, bp3, acc[i][3]);
            }
        }
    }
    float bvals[8];
#pragma unroll
    for (int j = 0; j < 8; j++) bvals[j] = __ldg(b_he + n0 + tx * 8 + j);
#pragma unroll
    for (int i = 0; i < 8; i++) {
        int row = m0 + ty * 8 + i;
        float out[8]; float2 v;
        v = up2(acc[i][0]); out[0] = v.x; out[1] = v.y;
        v = up2(acc[i][1]); out[2] = v.x; out[3] = v.y;
        v = up2(acc[i][2]); out[4] = v.x; out[5] = v.y;
        v = up2(acc[i][3]); out[6] = v.x; out[7] = v.y;
#pragma unroll
        for (int j = 0; j < 8; j++) out[j] = fmaxf(out[j] + bvals[j], 0.f);
        float4* dst = (float4*)(g_he + (size_t)row * SSZ + n0 + tx * 8);
        dst[0] = make_float4(out[0], out[1], out[2], out[3]);
        dst[1] = make_float4(out[4], out[5], out[6], out[7]);
    }
}

// ---------------- K3: persistent GRU, v5 ----------------
// 128 blocks x 1024 threads, 1 block/SM, 144KB dynamic smem.
// Thread = (iq = tid&63 -> batch rows 2iq,2iq+1 ; kq = tid>>6 -> 32 k-values).
// h loaded as native ull (float2 pair over batch rows, zero movs, zero duplication).
// Weights pre-duplicated pk2(w,w) in smem [k][uu][6] (uu = unit-pair), broadcast LDS.
// Per thread: 384 fma2, 32 LDG.64, 192 LDS.128, acc = 12 ull.
// Single-stage reduction (512 threads sum 16 kq partials per gate, fixed order).
__global__ void __launch_bounds__(1024, 1) k3_gru(const float* __restrict__ W_hh,
                                                  const float* __restrict__ b_hh) {
    extern __shared__ __align__(16) ull smemBuf[];
    ull* sW = smemBuf;                       // [(k*2+uu)*6 + up*3 + g]
    ull* sP = smemBuf + SW_ULL;              // [((kq*3+g)*4+u)*64 + iq]
    float* sPF = (float*)sP;                 // float view: [((kq*3+g)*4+u)*128 + i]

    const int tid = threadIdx.x;
    const int base = blockIdx.x * 4;

    // fill packed weights
    for (int e = tid; e < 6144; e += 1024) {
        int g = e % 3;
        int up = (e / 3) & 1;
        int uu = (e / 6) & 1;
        int k = e / 12;
        float w = W_hh[(size_t)(g * HSZ + base + 2 * uu + up) * HSZ + k];
        sW[(size_t)(k * 2 + uu) * 6 + up * 3 + g] = pk2(w, w);
    }

    const int iq = tid & 63;
    const int kq = tid >> 6;

    // stage-B identity (tid < 512): i = tid&127, u = tid>>7
    const int bi = tid & 127;
    const int bu = tid >> 7;
    float bR = 0.f, bZ = 0.f, bN = 0.f;
    if (tid < 512) {
        bR = __ldg(b_hh + base + bu);
        bZ = __ldg(b_hh + HSZ + base + bu);
        bN = __ldg(b_hh + 2 * HSZ + base + bu);
    }
    __syncthreads();

    for (int t = 0; t < NSTEP; t++) {
        const float* hT = g_hsT + (size_t)t * HS_SLICE;
        float* hTn = g_hsT + (size_t)(t + 1) * HS_SLICE;

        // prefetch stage-B operands early (hidden under main loop)
        float xr = 0.f, xz = 0.f, xn = 0.f, hp = 0.f;
        if (tid < 512) {
            const float* xb = g_xg + (size_t)t * G3 * BSZ + bi;
            xr = __ldg(xb + (size_t)(0 * HSZ + base + bu) * BSZ);
            xz = __ldg(xb + (size_t)(1 * HSZ + base + bu) * BSZ);
            xn = __ldg(xb + (size_t)(2 * HSZ + base + bu) * BSZ);
            hp = __ldg(hT + (size_t)(base + bu) * BSZ + bi);
        }

        ull acc[3][4];
#pragma unroll
        for (int g = 0; g < 3; g++)
#pragma unroll
            for (int u = 0; u < 4; u++) acc[g][u] = 0ull;

        const ull* hU = (const ull*)hT + (size_t)(kq * 32) * 64 + iq;   // 64 ull per k-row
        const ull* wK = sW + (size_t)(kq * 32) * 12;

#pragma unroll 2
        for (int c4 = 0; c4 < 8; c4++) {
            // batch 4 h loads for MLP
            ull h0 = __ldg(hU + (size_t)(4 * c4 + 0) * 64);
            ull h1 = __ldg(hU + (size_t)(4 * c4 + 1) * 64);
            ull h2 = __ldg(hU + (size_t)(4 * c4 + 2) * 64);
            ull h3 = __ldg(hU + (size_t)(4 * c4 + 3) * 64);
            ull hh[4] = {h0, h1, h2, h3};
#pragma unroll
            for (int cc = 0; cc < 4; cc++) {
                const ull* wp = wK + (size_t)(4 * c4 + cc) * 12;
                ull h = hh[cc];
#pragma unroll
                for (int uu = 0; uu < 2; uu++) {
                    ulonglong2 A = *(const ulonglong2*)(wp + uu * 6);      // u0g0,u0g1
                    ulonglong2 B = *(const ulonglong2*)(wp + uu * 6 + 2);  // u0g2,u1g0
                    ulonglong2 C = *(const ulonglong2*)(wp + uu * 6 + 4);  // u1g1,u1g2
                    acc[0][2 * uu + 0] = fma2(h, A.x, acc[0][2 * uu + 0]);
                    acc[1][2 * uu + 0] = fma2(h, A.y, acc[1][2 * uu + 0]);
                    acc[2][2 * uu + 0] = fma2(h, B.x, acc[2][2 * uu + 0]);
                    acc[0][2 * uu + 1] = fma2(h, B.y, acc[0][2 * uu + 1]);
                    acc[1][2 * uu + 1] = fma2(h, C.x, acc[1][2 * uu + 1]);
                    acc[2][2 * uu + 1] = fma2(h, C.y, acc[2][2 * uu + 1]);
                }
            }
        }
        // store partials: [((kq*3+g)*4+u)*64 + iq]
#pragma unroll
        for (int g = 0; g < 3; g++)
#pragma unroll
            for (int u = 0; u < 4; u++)
                sP[(size_t)(((kq * 3 + g) * 4 + u)) * 64 + iq] = acc[g][u];
        __syncthreads();

        // ---- single-stage reduce + nonlinearity (512 threads) ----
        if (tid < 512) {
            float hr = 0.f, hz = 0.f, hn = 0.f;
            const float* pb = sPF + (size_t)bu * 128 + bi;
#pragma unroll 4
            for (int q = 0; q < 16; q++) {
                const float* pq = pb + (size_t)(q * 3) * 512;     // (g stride = 4*128)
                hr += pq[0];
                hz += pq[512];
                hn += pq[1024];
            }
            float r = sigm(xr + hr + bR);
            float z = sigm(xz + hz + bZ);
            float n = tanhf(xn + r * (hn + bN));
            float o = (1.f - z) * n + z * hp;
            hTn[(size_t)(base + bu) * BSZ + bi] = o;
        }
        // ---- grid barrier ----
        __threadfence();
        __syncthreads();
        if (tid == 0) {
            atomicAdd(&g_arrive, 1u);
            unsigned target = (unsigned)NGRU_BLK * (unsigned)(t + 1);
            while (*(volatile unsigned*)&g_arrive < target) { __nanosleep(32); }
            __threadfence();
        }
        __syncthreads();
    }
}

// ---------------- K3t: transpose g_hsT [t][k][i] -> g_hs [t][i][k] ----------------
__global__ void __launch_bounds__(256) k3t_transpose() {
    __shared__ float tile[32][33];
    const int t = blockIdx.z;
    const int k0 = blockIdx.x * 32;
    const int i0 = blockIdx.y * 32;
    const int x = threadIdx.x & 31;
    const int y = threadIdx.x >> 5;          // 0..7
    const float* src = g_hsT + (size_t)t * HS_SLICE;
    float* dst = g_hs + (size_t)t * HS_SLICE;
#pragma unroll
    for (int r = 0; r < 4; r++)
        tile[y + 8 * r][x] = src[(size_t)(k0 + y + 8 * r) * BSZ + i0 + x];
    __syncthreads();
#pragma unroll
    for (int r = 0; r < 4; r++)
        dst[(size_t)(i0 + y + 8 * r) * HSZ + k0 + x] = tile[x][y + 8 * r];
}

// ---------------- K4b: per-event loss ----------------
__global__ void __launch_bounds__(256) k4b_loss(const float* __restrict__ x,
                                                const float* __restrict__ tin,
                                                const float* __restrict__ maskp,
                                                const float* __restrict__ W_mu,
                                                const float* __restrict__ b_mu,
                                                const float* __restrict__ W_lv,
                                                const float* __restrict__ b_lv,
                                                const float* __restrict__ h_infl,
                                                const float* __restrict__ ti_p,
                                                const float* __restrict__ bi_p) {
    __shared__ float s_he[8][SSZ];
    __shared__ float s_red[8];
    const int tid = threadIdx.x;
    const int w = tid >> 5, lane = tid & 31;
    const int q = blockIdx.x * 8 + w;
    const int t = (q >> 7) + 1;
    const int i = q & 127;
    const size_t row = (size_t)t * BSZ + i;

    ((float4*)s_he[w])[lane] = ((const float4*)(g_he + row * SSZ))[lane];
    __syncwarp();

    float p = 0.f;
#pragma unroll
    for (int kk = 0; kk < 4; kk++) {
        int k = lane + 32 * kk;
        p += s_he[w][k] * __ldg(h_infl + k);
    }
#pragma unroll
    for (int off = 16; off; off >>= 1) p += __shfl_xor_sync(0xffffffffu, p, off);

    float marker = 0.f;
    if (lane < MDIM) {
        float accm = __ldg(b_mu + lane);
        float accl = __ldg(b_lv + lane);
        const float4* wm = (const float4*)(W_mu + lane * SSZ);
        const float4* wl = (const float4*)(W_lv + lane * SSZ);
#pragma unroll 8
        for (int kk = 0; kk < 32; kk++) {
            float4 hev = ((const float4*)s_he[w])[kk];
            float4 a = __ldg(wm + kk);
            float4 b = __ldg(wl + kk);
            accm += hev.x * a.x + hev.y * a.y + hev.z * a.z + hev.w * a.w;
            accl += hev.x * b.x + hev.y * b.y + hev.z * b.z + hev.w * b.w;
        }
        float xv = __ldg(x + row * MDIM + lane);
        float sig = fmaxf(expf(0.5f * accl), 0.01f);
        float d = (xv - accm) / sig;
        marker = -0.5f * d * d - logf(sig) - 0.5f * LOG2PI;
    }
#pragma unroll
    for (int off = 16; off; off >>= 1) marker += __shfl_xor_sync(0xffffffffu, marker, off);

    if (lane == 0) {
        float ti = __ldg(ti_p);
        float bi = __ldg(bi_p);
        float dt = __ldg(tin + row * 2 + 1);
        float term1 = p + ti * dt + bi;
        float time_ll = term1 + (expf(p + bi) - expf(term1)) / ti;
        float m = __ldg(maskp + row);
        s_red[w] = (-time_ll - marker) * m;
    }
    __syncthreads();
    if (tid == 0) {
        float s = 0.f;
#pragma unroll
        for (int k = 0; k < 8; k++) s += s_red[k];
        g_partial[blockIdx.x] = s;
    }
}

// ---------------- K5: deterministic final reduce ----------------
__global__ void __launch_bounds__(256) k5_reduce(float* __restrict__ out) {
    __shared__ float s[256];
    const int tid = threadIdx.x;
    float a = 0.f;
    for (int idx = tid; idx < NB4B; idx += 256) a += g_partial[idx];
    s[tid] = a;
    __syncthreads();
    for (int off = 128; off; off >>= 1) {
        if (tid < off) s[tid] += s[tid + off];
        __syncthreads();
    }
    if (tid == 0) out[0] = s[0];
}

// ---------------- launch ----------------
extern "C" void kernel_launch(void* const* d_in, const int* in_sizes, int n_in,
                              void* d_out, int out_size) {
    const float* x       = (const float*)d_in[0];
    const float* tin     = (const float*)d_in[1];
    const float* maskp   = (const float*)d_in[2];
    const float* W_embed = (const float*)d_in[3];
    const float* b_embed = (const float*)d_in[4];
    const float* W_ih    = (const float*)d_in[5];
    const float* b_ih    = (const float*)d_in[6];
    const float* W_hh    = (const float*)d_in[7];
    const float* b_hh    = (const float*)d_in[8];
    const float* W_he    = (const float*)d_in[9];
    const float* b_he    = (const float*)d_in[10];
    const float* W_mu    = (const float*)d_in[11];
    const float* b_mu    = (const float*)d_in[12];
    const float* W_lv    = (const float*)d_in[13];
    const float* b_lv    = (const float*)d_in[14];
    const float* h_infl  = (const float*)d_in[15];
    const float* ti_p    = (const float*)d_in[16];
    const float* bi_p    = (const float*)d_in[17];
    float* out = (float*)d_out;

    static bool attr_set = false;
    if (!attr_set) {
        cudaFuncSetAttribute(k3_gru, cudaFuncAttributeMaxDynamicSharedMemorySize, K3_SMEM_BYTES);
        attr_set = true;
    }

    k0_init<<<256, 256>>>();
    k1_embed<<<1024, 256>>>(x, W_embed, b_embed);
    k2_gatesT<<<dim3(12, 1, 512), 256>>>(W_ih, b_ih);
    k3_gru<<<NGRU_BLK, 1024, K3_SMEM_BYTES>>>(W_hh, b_hh);
    k3t_transpose<<<dim3(16, 4, 512), 256>>>();
    k4a_he<<<dim3(512, 1), 256>>>(W_he, b_he);
    k4b_loss<<<NB4B, 256>>>(x, tin, maskp, W_mu, b_mu, W_lv, b_lv, h_infl, ti_p, bi_p);
    k5_reduce<<<1, 256>>>(out);
}